// round 11
// baseline (speedup 1.0000x reference)
#include <cuda_runtime.h>
#include <cuda_bf16.h>
#include <math_constants.h>

#define DIM 4096
#define CAP 8192
#define VEC (DIM / 4)      // 1024 float4 per row
#define MAXK 64
#define GRID_S 592         // 4 blocks/SM x 148 SMs, single wave

// Scratch (no allocations allowed)
__device__ float g_scores[CAP];
__device__ float g_retrieved[DIM];

// ---------------------------------------------------------------------------
// 512-thread block reduce of 2 values. Trailing barrier so the helper can be
// called repeatedly in a loop without smem races.
// ---------------------------------------------------------------------------
__device__ __forceinline__ void block_reduce2_512(float& a, float& b) {
    __shared__ float sa[16], sb[16];
    int lane = threadIdx.x & 31;
    int wid  = threadIdx.x >> 5;
    #pragma unroll
    for (int off = 16; off > 0; off >>= 1) {
        a += __shfl_down_sync(0xffffffffu, a, off);
        b += __shfl_down_sync(0xffffffffu, b, off);
    }
    if (lane == 0) { sa[wid] = a; sb[wid] = b; }
    __syncthreads();
    if (wid == 0) {
        a = (lane < 16) ? sa[lane] : 0.0f;
        b = (lane < 16) ? sb[lane] : 0.0f;
        #pragma unroll
        for (int off = 8; off > 0; off >>= 1) {
            a += __shfl_down_sync(0xffffffffu, a, off);
            b += __shfl_down_sync(0xffffffffu, b, off);
        }
    }
    __syncthreads();
}

// ---------------------------------------------------------------------------
// Kernel 1: persistent-CTA weighted cosine scores + smooth W_dec L2 prefetch.
// q lives in registers for the whole block (no q reloads -> half the L1
// wavefront pressure). Prefetch cursor runs so W rows decoded FIRST are
// prefetched LAST (freshest in L2).
// ---------------------------------------------------------------------------
__global__ void __launch_bounds__(512, 4)
scores_kernel(const float* __restrict__ query,
              const float* __restrict__ memory_bank,
              const float* __restrict__ importance,
              const float* __restrict__ age,
              const float* __restrict__ W_dec) {
    cudaTriggerProgrammaticLaunchCompletion();
    int tid = threadIdx.x;
    __shared__ float qn_s;

    // load q once into registers (2 float4 per thread)
    const float4* q4 = reinterpret_cast<const float4*>(query);
    float4 q0 = q4[tid];
    float4 q1 = q4[tid + 512];

    // block-wide ||q||^2, once
    {
        float qsq = q0.x * q0.x + q0.y * q0.y + q0.z * q0.z + q0.w * q0.w
                  + q1.x * q1.x + q1.y * q1.y + q1.z * q1.z + q1.w * q1.w;
        float dz = 0.0f;
        block_reduce2_512(qsq, dz);
        if (tid == 0) qn_s = sqrtf(qsq);
        __syncthreads();
    }
    float qn = qn_s;

    const char* wbase = reinterpret_cast<const char*>(W_dec);

    int t = 0;
    for (int row = blockIdx.x; row < CAP; row += GRID_S, t++) {
        // issue importance/age early (t0 only) so latency hides under stream
        float imp = 0.0f, ag = 0.0f;
        if (tid == 0) { imp = importance[row]; ag = age[row]; }

        const float4* m4 =
            reinterpret_cast<const float4*>(memory_bank + (size_t)row * DIM);
        float4 a = __ldcs(m4 + tid);
        float4 b = __ldcs(m4 + tid + 512);

        // smooth reverse-order W prefetch: one 8KB slice per row-iteration
        int s = 8287 - (t * GRID_S + (int)blockIdx.x);
        if (s >= 0 && s < 8192 && tid < 64) {
            asm volatile("prefetch.global.L2 [%0];"
                         :: "l"(wbase + (size_t)s * 8192 + (size_t)tid * 128));
        }

        float dot = q0.x * a.x + q0.y * a.y + q0.z * a.z + q0.w * a.w
                  + q1.x * b.x + q1.y * b.y + q1.z * b.z + q1.w * b.w;
        float msq = a.x * a.x + a.y * a.y + a.z * a.z + a.w * a.w
                  + b.x * b.x + b.y * b.y + b.z * b.z + b.w * b.w;

        block_reduce2_512(dot, msq);
        if (tid == 0) {
            float denom = fmaxf(qn * sqrtf(msq), 1e-8f);
            g_scores[row] = (dot / denom) * imp * expf(-0.001f * ag);
        }
    }
}

// ---------------------------------------------------------------------------
// Kernel 2: top-k + mean pool. Single block, PDL consumer. (R10-proven)
// Tie-break matches jax.lax.top_k (smaller index wins on equal value).
// ---------------------------------------------------------------------------
__device__ __forceinline__ bool cmp_gt(float av, int ai, float bv, int bi) {
    return (av > bv) || (av == bv && ai < bi);
}

__global__ void __launch_bounds__(256, 1)
topk_mean_kernel(const float* __restrict__ memory_bank,
                 const int* __restrict__ top_k_ptr) {
    __shared__ float s[CAP];                         // 32 KB staged scores
    __shared__ int   chosen[MAXK];
    __shared__ float rv[256];
    __shared__ int   ri[256];

    cudaTriggerProgrammaticLaunchCompletion();
    cudaGridDependencySynchronize();

    int tid = threadIdx.x;

    #pragma unroll
    for (int t = 0; t < CAP / 256; t++) {
        int i = tid + (t << 8);
        s[i] = g_scores[i];
    }
    __syncthreads();

    int k = top_k_ptr[0];
    if (k < 1) k = 1;
    if (k > MAXK) k = MAXK;

    if (k <= 8) {
        float lv[8]; int li[8];
        #pragma unroll
        for (int j = 0; j < 8; j++) { lv[j] = -CUDART_INF_F; li[j] = CAP + j; }

        #pragma unroll 4
        for (int t = 0; t < CAP / 256; t++) {
            int i = tid + (t << 8);
            float v = s[i];
            if (cmp_gt(v, i, lv[7], li[7])) {
                lv[7] = v; li[7] = i;
                #pragma unroll
                for (int j = 7; j > 0; j--) {
                    if (cmp_gt(lv[j], li[j], lv[j-1], li[j-1])) {
                        float tv = lv[j]; lv[j] = lv[j-1]; lv[j-1] = tv;
                        int   ti = li[j]; li[j] = li[j-1]; li[j-1] = ti;
                    }
                }
            }
        }
        __syncthreads();

        float (*sv)[8] = reinterpret_cast<float(*)[8]>(s);
        int   (*si)[8] = reinterpret_cast<int(*)[8]>(s + 2048);
        #pragma unroll
        for (int j = 0; j < 8; j++) { sv[tid][j] = lv[j]; si[tid][j] = li[j]; }
        __syncthreads();

        for (int stride = 128; stride >= 1; stride >>= 1) {
            bool active = (tid < stride);
            float mv[8]; int mi[8];
            if (active) {
                int pa = 0, pb = 0;
                #pragma unroll
                for (int j = 0; j < 8; j++) {
                    float av = sv[tid][pa];          int ai = si[tid][pa];
                    float bv = sv[tid + stride][pb]; int bi = si[tid + stride][pb];
                    if (cmp_gt(av, ai, bv, bi)) { mv[j] = av; mi[j] = ai; pa++; }
                    else                        { mv[j] = bv; mi[j] = bi; pb++; }
                }
            }
            __syncthreads();
            if (active) {
                #pragma unroll
                for (int j = 0; j < 8; j++) { sv[tid][j] = mv[j]; si[tid][j] = mi[j]; }
            }
            __syncthreads();
        }
        if (tid < k) chosen[tid] = si[0][tid];
        __syncthreads();
    } else {
        for (int r = 0; r < k; r++) {
            float best = -CUDART_INF_F; int bi = CAP;
            for (int i = tid; i < CAP; i += 256) {
                float v = s[i];
                if (v > best) { best = v; bi = i; }
            }
            rv[tid] = best; ri[tid] = bi;
            __syncthreads();
            for (int off = 128; off > 0; off >>= 1) {
                if (tid < off) {
                    float ov = rv[tid + off]; int oi = ri[tid + off];
                    if (ov > rv[tid] || (ov == rv[tid] && oi < ri[tid])) {
                        rv[tid] = ov; ri[tid] = oi;
                    }
                }
                __syncthreads();
            }
            if (tid == 0) { chosen[r] = ri[0]; s[ri[0]] = -CUDART_INF_F; }
            __syncthreads();
        }
    }

    float invk = 1.0f / (float)k;
    for (int j = tid; j < VEC; j += 256) {
        float4 acc = make_float4(0.f, 0.f, 0.f, 0.f);
        for (int r = 0; r < k; r++) {
            const float4* row4 =
                reinterpret_cast<const float4*>(memory_bank + (size_t)chosen[r] * DIM);
            float4 v = row4[j];
            acc.x += v.x; acc.y += v.y; acc.z += v.z; acc.w += v.w;
        }
        reinterpret_cast<float4*>(g_retrieved)[j] =
            make_float4(acc.x * invk, acc.y * invk, acc.z * invk, acc.w * invk);
    }
}

// ---------------------------------------------------------------------------
// Kernel 3: out[i] = b[i] + W[i] . retrieved. PDL consumer; W from L2.
// ---------------------------------------------------------------------------
__device__ __forceinline__ void block_reduce1(float& a) {
    __shared__ float sa[8];
    int lane = threadIdx.x & 31;
    int wid  = threadIdx.x >> 5;
    #pragma unroll
    for (int off = 16; off > 0; off >>= 1)
        a += __shfl_down_sync(0xffffffffu, a, off);
    if (lane == 0) sa[wid] = a;
    __syncthreads();
    if (wid == 0) {
        a = (lane < 8) ? sa[lane] : 0.0f;
        #pragma unroll
        for (int off = 4; off > 0; off >>= 1)
            a += __shfl_down_sync(0xffffffffu, a, off);
    }
}

__global__ void __launch_bounds__(256, 6)
decode_kernel(const float* __restrict__ W_dec,
              const float* __restrict__ b_dec,
              float* __restrict__ out) {
    int row = blockIdx.x;
    const float4* w4 = reinterpret_cast<const float4*>(W_dec + (size_t)row * DIM);
    const float4* r4 = reinterpret_cast<const float4*>(g_retrieved);

    // prefetch W row into registers (overlaps topk via PDL)
    float4 w[4];
    #pragma unroll
    for (int i = 0; i < VEC / 256; i++) {
        w[i] = w4[threadIdx.x + (i << 8)];
    }

    cudaGridDependencySynchronize();   // g_retrieved now valid

    float acc = 0.0f;
    #pragma unroll
    for (int i = 0; i < VEC / 256; i++) {
        float4 r = r4[threadIdx.x + (i << 8)];
        acc += w[i].x * r.x + w[i].y * r.y + w[i].z * r.z + w[i].w * r.w;
    }
    block_reduce1(acc);
    if (threadIdx.x == 0) out[row] = acc + b_dec[row];
}

// ---------------------------------------------------------------------------
extern "C" void kernel_launch(void* const* d_in, const int* in_sizes, int n_in,
                              void* d_out, int out_size) {
    const float* query       = (const float*)d_in[0];
    const float* memory_bank = (const float*)d_in[1];
    const float* importance  = (const float*)d_in[2];
    const float* age         = (const float*)d_in[3];
    const float* W_dec       = (const float*)d_in[4];
    const float* b_dec       = (const float*)d_in[5];
    const int*   top_k       = (const int*)d_in[6];
    float* out = (float*)d_out;

    scores_kernel<<<GRID_S, 512>>>(query, memory_bank, importance, age, W_dec);

    cudaLaunchAttribute pdl_attr[1];
    pdl_attr[0].id = cudaLaunchAttributeProgrammaticStreamSerialization;
    pdl_attr[0].val.programmaticStreamSerializationAllowed = 1;

    {
        cudaLaunchConfig_t cfg = {};
        cfg.gridDim  = dim3(1, 1, 1);
        cfg.blockDim = dim3(256, 1, 1);
        cfg.attrs    = pdl_attr;
        cfg.numAttrs = 1;
        cudaLaunchKernelEx(&cfg, topk_mean_kernel, memory_bank, top_k);
    }
    {
        cudaLaunchConfig_t cfg = {};
        cfg.gridDim  = dim3(DIM, 1, 1);
        cfg.blockDim = dim3(256, 1, 1);
        cfg.attrs    = pdl_attr;
        cfg.numAttrs = 1;
        cudaLaunchKernelEx(&cfg, decode_kernel, W_dec, b_dec, out);
    }
}

// round 12
// speedup vs baseline: 1.0280x; 1.0280x over previous
#include <cuda_runtime.h>
#include <cuda_bf16.h>
#include <math_constants.h>

#define DIM 4096
#define CAP 8192
#define VEC (DIM / 4)      // 1024 float4 per row
#define MAXK 64

// Scratch (no allocations allowed)
__device__ float g_scores[CAP];
__device__ float g_retrieved[DIM];

// ---------------------------------------------------------------------------
// Block-wide 3-value sum reduction helper (warp shuffle + smem)
// ---------------------------------------------------------------------------
__device__ __forceinline__ void block_reduce3(float& a, float& b, float& c) {
    __shared__ float sa[8], sb[8], sc[8];
    int lane = threadIdx.x & 31;
    int wid  = threadIdx.x >> 5;
    #pragma unroll
    for (int off = 16; off > 0; off >>= 1) {
        a += __shfl_down_sync(0xffffffffu, a, off);
        b += __shfl_down_sync(0xffffffffu, b, off);
        c += __shfl_down_sync(0xffffffffu, c, off);
    }
    if (lane == 0) { sa[wid] = a; sb[wid] = b; sc[wid] = c; }
    __syncthreads();
    if (wid == 0) {
        int nw = blockDim.x >> 5;
        a = (lane < nw) ? sa[lane] : 0.0f;
        b = (lane < nw) ? sb[lane] : 0.0f;
        c = (lane < nw) ? sc[lane] : 0.0f;
        #pragma unroll
        for (int off = 4; off > 0; off >>= 1) {
            a += __shfl_down_sync(0xffffffffu, a, off);
            b += __shfl_down_sync(0xffffffffu, b, off);
            c += __shfl_down_sync(0xffffffffu, c, off);
        }
    }
}

// 5-value reduce for the double-row scores epilogue (256 threads)
__device__ __forceinline__ void block_reduce5(float& a, float& b, float& c,
                                              float& d, float& e) {
    __shared__ float sa[8], sb[8], sc[8], sd[8], se[8];
    int lane = threadIdx.x & 31;
    int wid  = threadIdx.x >> 5;
    #pragma unroll
    for (int off = 16; off > 0; off >>= 1) {
        a += __shfl_down_sync(0xffffffffu, a, off);
        b += __shfl_down_sync(0xffffffffu, b, off);
        c += __shfl_down_sync(0xffffffffu, c, off);
        d += __shfl_down_sync(0xffffffffu, d, off);
        e += __shfl_down_sync(0xffffffffu, e, off);
    }
    if (lane == 0) { sa[wid] = a; sb[wid] = b; sc[wid] = c; sd[wid] = d; se[wid] = e; }
    __syncthreads();
    if (wid == 0) {
        a = (lane < 8) ? sa[lane] : 0.0f;
        b = (lane < 8) ? sb[lane] : 0.0f;
        c = (lane < 8) ? sc[lane] : 0.0f;
        d = (lane < 8) ? sd[lane] : 0.0f;
        e = (lane < 8) ? se[lane] : 0.0f;
        #pragma unroll
        for (int off = 4; off > 0; off >>= 1) {
            a += __shfl_down_sync(0xffffffffu, a, off);
            b += __shfl_down_sync(0xffffffffu, b, off);
            c += __shfl_down_sync(0xffffffffu, c, off);
            d += __shfl_down_sync(0xffffffffu, d, off);
            e += __shfl_down_sync(0xffffffffu, e, off);
        }
    }
}

// ---------------------------------------------------------------------------
// Kernel 1: weighted cosine scores, block per TWO rows, 8 front-batched
// __ldcs loads per thread (384 outstanding loads/SM vs 256 in R10), plus
// W_dec L2 prefetch (2 slices per block, same total as R10).
// ---------------------------------------------------------------------------
__global__ void __launch_bounds__(256, 6)
scores_kernel(const float* __restrict__ query,
              const float* __restrict__ memory_bank,
              const float* __restrict__ importance,
              const float* __restrict__ age,
              const float* __restrict__ W_dec) {
    cudaTriggerProgrammaticLaunchCompletion();
    int row0 = blockIdx.x * 2;
    int row1 = row0 + 1;
    int tid = threadIdx.x;

    // prefetch this block's two 8KB W_dec slices into L2 (128 x 128B lines)
    const char* wslice = reinterpret_cast<const char*>(W_dec)
                       + (size_t)blockIdx.x * 16384;
    if (tid < 128) {
        asm volatile("prefetch.global.L2 [%0];"
                     :: "l"(wslice + (size_t)tid * 128));
    }

    const float4* q4 = reinterpret_cast<const float4*>(query);
    const float4* m0 = reinterpret_cast<const float4*>(memory_bank + (size_t)row0 * DIM);
    const float4* m1 = reinterpret_cast<const float4*>(memory_bank + (size_t)row1 * DIM);

    // front-batch 8 independent streamed loads
    float4 a0 = __ldcs(m0 + tid);
    float4 a1 = __ldcs(m0 + tid + 256);
    float4 a2 = __ldcs(m0 + tid + 512);
    float4 a3 = __ldcs(m0 + tid + 768);
    float4 b0 = __ldcs(m1 + tid);
    float4 b1 = __ldcs(m1 + tid + 256);
    float4 b2 = __ldcs(m1 + tid + 512);
    float4 b3 = __ldcs(m1 + tid + 768);
    float4 q0 = q4[tid];
    float4 q1 = q4[tid + 256];
    float4 q2 = q4[tid + 512];
    float4 q3 = q4[tid + 768];

    float dot0 = q0.x*a0.x + q0.y*a0.y + q0.z*a0.z + q0.w*a0.w
               + q1.x*a1.x + q1.y*a1.y + q1.z*a1.z + q1.w*a1.w
               + q2.x*a2.x + q2.y*a2.y + q2.z*a2.z + q2.w*a2.w
               + q3.x*a3.x + q3.y*a3.y + q3.z*a3.z + q3.w*a3.w;
    float msq0 = a0.x*a0.x + a0.y*a0.y + a0.z*a0.z + a0.w*a0.w
               + a1.x*a1.x + a1.y*a1.y + a1.z*a1.z + a1.w*a1.w
               + a2.x*a2.x + a2.y*a2.y + a2.z*a2.z + a2.w*a2.w
               + a3.x*a3.x + a3.y*a3.y + a3.z*a3.z + a3.w*a3.w;
    float dot1 = q0.x*b0.x + q0.y*b0.y + q0.z*b0.z + q0.w*b0.w
               + q1.x*b1.x + q1.y*b1.y + q1.z*b1.z + q1.w*b1.w
               + q2.x*b2.x + q2.y*b2.y + q2.z*b2.z + q2.w*b2.w
               + q3.x*b3.x + q3.y*b3.y + q3.z*b3.z + q3.w*b3.w;
    float msq1 = b0.x*b0.x + b0.y*b0.y + b0.z*b0.z + b0.w*b0.w
               + b1.x*b1.x + b1.y*b1.y + b1.z*b1.z + b1.w*b1.w
               + b2.x*b2.x + b2.y*b2.y + b2.z*b2.z + b2.w*b2.w
               + b3.x*b3.x + b3.y*b3.y + b3.z*b3.z + b3.w*b3.w;
    float qsq = q0.x*q0.x + q0.y*q0.y + q0.z*q0.z + q0.w*q0.w
              + q1.x*q1.x + q1.y*q1.y + q1.z*q1.z + q1.w*q1.w
              + q2.x*q2.x + q2.y*q2.y + q2.z*q2.z + q2.w*q2.w
              + q3.x*q3.x + q3.y*q3.y + q3.z*q3.z + q3.w*q3.w;

    block_reduce5(dot0, msq0, dot1, msq1, qsq);
    if (tid == 0) {
        float qn = sqrtf(qsq);
        float s0 = dot0 / fmaxf(qn * sqrtf(msq0), 1e-8f);
        float s1 = dot1 / fmaxf(qn * sqrtf(msq1), 1e-8f);
        g_scores[row0] = s0 * importance[row0] * expf(-0.001f * age[row0]);
        g_scores[row1] = s1 * importance[row1] * expf(-0.001f * age[row1]);
    }
}

// ---------------------------------------------------------------------------
// Kernel 2: top-k + mean pool. Single block, PDL consumer. (R10-proven)
// Tie-break matches jax.lax.top_k (smaller index wins on equal value).
// ---------------------------------------------------------------------------
__device__ __forceinline__ bool cmp_gt(float av, int ai, float bv, int bi) {
    return (av > bv) || (av == bv && ai < bi);
}

__global__ void __launch_bounds__(256, 1)
topk_mean_kernel(const float* __restrict__ memory_bank,
                 const int* __restrict__ top_k_ptr) {
    __shared__ float s[CAP];                         // 32 KB staged scores
    __shared__ int   chosen[MAXK];
    __shared__ float rv[256];
    __shared__ int   ri[256];

    cudaTriggerProgrammaticLaunchCompletion();
    cudaGridDependencySynchronize();

    int tid = threadIdx.x;

    #pragma unroll
    for (int t = 0; t < CAP / 256; t++) {
        int i = tid + (t << 8);
        s[i] = g_scores[i];
    }
    __syncthreads();

    int k = top_k_ptr[0];
    if (k < 1) k = 1;
    if (k > MAXK) k = MAXK;

    if (k <= 8) {
        float lv[8]; int li[8];
        #pragma unroll
        for (int j = 0; j < 8; j++) { lv[j] = -CUDART_INF_F; li[j] = CAP + j; }

        #pragma unroll 4
        for (int t = 0; t < CAP / 256; t++) {
            int i = tid + (t << 8);
            float v = s[i];
            if (cmp_gt(v, i, lv[7], li[7])) {
                lv[7] = v; li[7] = i;
                #pragma unroll
                for (int j = 7; j > 0; j--) {
                    if (cmp_gt(lv[j], li[j], lv[j-1], li[j-1])) {
                        float tv = lv[j]; lv[j] = lv[j-1]; lv[j-1] = tv;
                        int   ti = li[j]; li[j] = li[j-1]; li[j-1] = ti;
                    }
                }
            }
        }
        __syncthreads();

        float (*sv)[8] = reinterpret_cast<float(*)[8]>(s);
        int   (*si)[8] = reinterpret_cast<int(*)[8]>(s + 2048);
        #pragma unroll
        for (int j = 0; j < 8; j++) { sv[tid][j] = lv[j]; si[tid][j] = li[j]; }
        __syncthreads();

        for (int stride = 128; stride >= 1; stride >>= 1) {
            bool active = (tid < stride);
            float mv[8]; int mi[8];
            if (active) {
                int pa = 0, pb = 0;
                #pragma unroll
                for (int j = 0; j < 8; j++) {
                    float av = sv[tid][pa];          int ai = si[tid][pa];
                    float bv = sv[tid + stride][pb]; int bi = si[tid + stride][pb];
                    if (cmp_gt(av, ai, bv, bi)) { mv[j] = av; mi[j] = ai; pa++; }
                    else                        { mv[j] = bv; mi[j] = bi; pb++; }
                }
            }
            __syncthreads();
            if (active) {
                #pragma unroll
                for (int j = 0; j < 8; j++) { sv[tid][j] = mv[j]; si[tid][j] = mi[j]; }
            }
            __syncthreads();
        }
        if (tid < k) chosen[tid] = si[0][tid];
        __syncthreads();
    } else {
        for (int r = 0; r < k; r++) {
            float best = -CUDART_INF_F; int bi = CAP;
            for (int i = tid; i < CAP; i += 256) {
                float v = s[i];
                if (v > best) { best = v; bi = i; }
            }
            rv[tid] = best; ri[tid] = bi;
            __syncthreads();
            for (int off = 128; off > 0; off >>= 1) {
                if (tid < off) {
                    float ov = rv[tid + off]; int oi = ri[tid + off];
                    if (ov > rv[tid] || (ov == rv[tid] && oi < ri[tid])) {
                        rv[tid] = ov; ri[tid] = oi;
                    }
                }
                __syncthreads();
            }
            if (tid == 0) { chosen[r] = ri[0]; s[ri[0]] = -CUDART_INF_F; }
            __syncthreads();
        }
    }

    float invk = 1.0f / (float)k;
    for (int j = tid; j < VEC; j += 256) {
        float4 acc = make_float4(0.f, 0.f, 0.f, 0.f);
        for (int r = 0; r < k; r++) {
            const float4* row4 =
                reinterpret_cast<const float4*>(memory_bank + (size_t)chosen[r] * DIM);
            float4 v = row4[j];
            acc.x += v.x; acc.y += v.y; acc.z += v.z; acc.w += v.w;
        }
        reinterpret_cast<float4*>(g_retrieved)[j] =
            make_float4(acc.x * invk, acc.y * invk, acc.z * invk, acc.w * invk);
    }
}

// ---------------------------------------------------------------------------
// Kernel 3: out[i] = b[i] + W[i] . retrieved. PDL consumer; W from L2.
// (byte-for-byte R10)
// ---------------------------------------------------------------------------
__global__ void __launch_bounds__(256, 6)
decode_kernel(const float* __restrict__ W_dec,
              const float* __restrict__ b_dec,
              float* __restrict__ out) {
    int row = blockIdx.x;
    const float4* w4 = reinterpret_cast<const float4*>(W_dec + (size_t)row * DIM);
    const float4* r4 = reinterpret_cast<const float4*>(g_retrieved);

    // prefetch W row: 4 independent LDG.128 per thread (L2 hits expected)
    float4 w[4];
    #pragma unroll
    for (int i = 0; i < VEC / 256; i++) {
        w[i] = w4[threadIdx.x + (i << 8)];
    }

    cudaGridDependencySynchronize();   // g_retrieved now valid

    float acc = 0.0f, d1 = 0.0f, d2 = 0.0f;
    #pragma unroll
    for (int i = 0; i < VEC / 256; i++) {
        float4 r = r4[threadIdx.x + (i << 8)];
        acc += w[i].x * r.x + w[i].y * r.y + w[i].z * r.z + w[i].w * r.w;
    }
    block_reduce3(acc, d1, d2);
    if (threadIdx.x == 0) out[row] = acc + b_dec[row];
}

// ---------------------------------------------------------------------------
extern "C" void kernel_launch(void* const* d_in, const int* in_sizes, int n_in,
                              void* d_out, int out_size) {
    const float* query       = (const float*)d_in[0];
    const float* memory_bank = (const float*)d_in[1];
    const float* importance  = (const float*)d_in[2];
    const float* age         = (const float*)d_in[3];
    const float* W_dec       = (const float*)d_in[4];
    const float* b_dec       = (const float*)d_in[5];
    const int*   top_k       = (const int*)d_in[6];
    float* out = (float*)d_out;

    scores_kernel<<<CAP / 2, 256>>>(query, memory_bank, importance, age, W_dec);

    cudaLaunchAttribute pdl_attr[1];
    pdl_attr[0].id = cudaLaunchAttributeProgrammaticStreamSerialization;
    pdl_attr[0].val.programmaticStreamSerializationAllowed = 1;

    {
        cudaLaunchConfig_t cfg = {};
        cfg.gridDim  = dim3(1, 1, 1);
        cfg.blockDim = dim3(256, 1, 1);
        cfg.attrs    = pdl_attr;
        cfg.numAttrs = 1;
        cudaLaunchKernelEx(&cfg, topk_mean_kernel, memory_bank, top_k);
    }
    {
        cudaLaunchConfig_t cfg = {};
        cfg.gridDim  = dim3(DIM, 1, 1);
        cfg.blockDim = dim3(256, 1, 1);
        cfg.attrs    = pdl_attr;
        cfg.numAttrs = 1;
        cudaLaunchKernelEx(&cfg, decode_kernel, W_dec, b_dec, out);
    }
}

// round 13
// speedup vs baseline: 1.0628x; 1.0339x over previous
#include <cuda_runtime.h>
#include <cuda_bf16.h>
#include <math_constants.h>

#define DIM 4096
#define CAP 8192
#define VEC (DIM / 4)      // 1024 float4 per row
#define MAXK 64

// Scratch (no allocations allowed)
__device__ float g_scores[CAP];
__device__ float g_retrieved[DIM];

// ---------------------------------------------------------------------------
// Reduction helpers (256 threads)
// ---------------------------------------------------------------------------
__device__ __forceinline__ void block_reduce4(float& a, float& b, float& c, float& d) {
    __shared__ float sa[8], sb[8], sc[8], sd[8];
    int lane = threadIdx.x & 31;
    int wid  = threadIdx.x >> 5;
    #pragma unroll
    for (int off = 16; off > 0; off >>= 1) {
        a += __shfl_down_sync(0xffffffffu, a, off);
        b += __shfl_down_sync(0xffffffffu, b, off);
        c += __shfl_down_sync(0xffffffffu, c, off);
        d += __shfl_down_sync(0xffffffffu, d, off);
    }
    if (lane == 0) { sa[wid] = a; sb[wid] = b; sc[wid] = c; sd[wid] = d; }
    __syncthreads();
    if (wid == 0) {
        a = (lane < 8) ? sa[lane] : 0.0f;
        b = (lane < 8) ? sb[lane] : 0.0f;
        c = (lane < 8) ? sc[lane] : 0.0f;
        d = (lane < 8) ? sd[lane] : 0.0f;
        #pragma unroll
        for (int off = 4; off > 0; off >>= 1) {
            a += __shfl_down_sync(0xffffffffu, a, off);
            b += __shfl_down_sync(0xffffffffu, b, off);
            c += __shfl_down_sync(0xffffffffu, c, off);
            d += __shfl_down_sync(0xffffffffu, d, off);
        }
    }
}

__device__ __forceinline__ void block_reduce5(float& a, float& b, float& c,
                                              float& d, float& e) {
    __shared__ float sa[8], sb[8], sc[8], sd[8], se[8];
    int lane = threadIdx.x & 31;
    int wid  = threadIdx.x >> 5;
    #pragma unroll
    for (int off = 16; off > 0; off >>= 1) {
        a += __shfl_down_sync(0xffffffffu, a, off);
        b += __shfl_down_sync(0xffffffffu, b, off);
        c += __shfl_down_sync(0xffffffffu, c, off);
        d += __shfl_down_sync(0xffffffffu, d, off);
        e += __shfl_down_sync(0xffffffffu, e, off);
    }
    if (lane == 0) { sa[wid] = a; sb[wid] = b; sc[wid] = c; sd[wid] = d; se[wid] = e; }
    __syncthreads();
    if (wid == 0) {
        a = (lane < 8) ? sa[lane] : 0.0f;
        b = (lane < 8) ? sb[lane] : 0.0f;
        c = (lane < 8) ? sc[lane] : 0.0f;
        d = (lane < 8) ? sd[lane] : 0.0f;
        e = (lane < 8) ? se[lane] : 0.0f;
        #pragma unroll
        for (int off = 4; off > 0; off >>= 1) {
            a += __shfl_down_sync(0xffffffffu, a, off);
            b += __shfl_down_sync(0xffffffffu, b, off);
            c += __shfl_down_sync(0xffffffffu, c, off);
            d += __shfl_down_sync(0xffffffffu, d, off);
            e += __shfl_down_sync(0xffffffffu, e, off);
        }
    }
}

// ---------------------------------------------------------------------------
// Kernel 1: weighted cosine scores, block per TWO rows, 8 front-batched
// __ldcs loads per thread + W_dec L2 prefetch. (R12-proven: 33.9us, 74% DRAM)
// ---------------------------------------------------------------------------
__global__ void __launch_bounds__(256, 6)
scores_kernel(const float* __restrict__ query,
              const float* __restrict__ memory_bank,
              const float* __restrict__ importance,
              const float* __restrict__ age,
              const float* __restrict__ W_dec) {
    cudaTriggerProgrammaticLaunchCompletion();
    int row0 = blockIdx.x * 2;
    int row1 = row0 + 1;
    int tid = threadIdx.x;

    // prefetch this block's two 8KB W_dec slices into L2 (128 x 128B lines)
    const char* wslice = reinterpret_cast<const char*>(W_dec)
                       + (size_t)blockIdx.x * 16384;
    if (tid < 128) {
        asm volatile("prefetch.global.L2 [%0];"
                     :: "l"(wslice + (size_t)tid * 128));
    }

    const float4* q4 = reinterpret_cast<const float4*>(query);
    const float4* m0 = reinterpret_cast<const float4*>(memory_bank + (size_t)row0 * DIM);
    const float4* m1 = reinterpret_cast<const float4*>(memory_bank + (size_t)row1 * DIM);

    // front-batch 8 independent streamed loads
    float4 a0 = __ldcs(m0 + tid);
    float4 a1 = __ldcs(m0 + tid + 256);
    float4 a2 = __ldcs(m0 + tid + 512);
    float4 a3 = __ldcs(m0 + tid + 768);
    float4 b0 = __ldcs(m1 + tid);
    float4 b1 = __ldcs(m1 + tid + 256);
    float4 b2 = __ldcs(m1 + tid + 512);
    float4 b3 = __ldcs(m1 + tid + 768);
    float4 q0 = q4[tid];
    float4 q1 = q4[tid + 256];
    float4 q2 = q4[tid + 512];
    float4 q3 = q4[tid + 768];

    float dot0 = q0.x*a0.x + q0.y*a0.y + q0.z*a0.z + q0.w*a0.w
               + q1.x*a1.x + q1.y*a1.y + q1.z*a1.z + q1.w*a1.w
               + q2.x*a2.x + q2.y*a2.y + q2.z*a2.z + q2.w*a2.w
               + q3.x*a3.x + q3.y*a3.y + q3.z*a3.z + q3.w*a3.w;
    float msq0 = a0.x*a0.x + a0.y*a0.y + a0.z*a0.z + a0.w*a0.w
               + a1.x*a1.x + a1.y*a1.y + a1.z*a1.z + a1.w*a1.w
               + a2.x*a2.x + a2.y*a2.y + a2.z*a2.z + a2.w*a2.w
               + a3.x*a3.x + a3.y*a3.y + a3.z*a3.z + a3.w*a3.w;
    float dot1 = q0.x*b0.x + q0.y*b0.y + q0.z*b0.z + q0.w*b0.w
               + q1.x*b1.x + q1.y*b1.y + q1.z*b1.z + q1.w*b1.w
               + q2.x*b2.x + q2.y*b2.y + q2.z*b2.z + q2.w*b2.w
               + q3.x*b3.x + q3.y*b3.y + q3.z*b3.z + q3.w*b3.w;
    float msq1 = b0.x*b0.x + b0.y*b0.y + b0.z*b0.z + b0.w*b0.w
               + b1.x*b1.x + b1.y*b1.y + b1.z*b1.z + b1.w*b1.w
               + b2.x*b2.x + b2.y*b2.y + b2.z*b2.z + b2.w*b2.w
               + b3.x*b3.x + b3.y*b3.y + b3.z*b3.z + b3.w*b3.w;
    float qsq = q0.x*q0.x + q0.y*q0.y + q0.z*q0.z + q0.w*q0.w
              + q1.x*q1.x + q1.y*q1.y + q1.z*q1.z + q1.w*q1.w
              + q2.x*q2.x + q2.y*q2.y + q2.z*q2.z + q2.w*q2.w
              + q3.x*q3.x + q3.y*q3.y + q3.z*q3.z + q3.w*q3.w;

    block_reduce5(dot0, msq0, dot1, msq1, qsq);
    if (tid == 0) {
        float qn = sqrtf(qsq);
        float s0 = dot0 / fmaxf(qn * sqrtf(msq0), 1e-8f);
        float s1 = dot1 / fmaxf(qn * sqrtf(msq1), 1e-8f);
        g_scores[row0] = s0 * importance[row0] * expf(-0.001f * age[row0]);
        g_scores[row1] = s1 * importance[row1] * expf(-0.001f * age[row1]);
    }
}

// ---------------------------------------------------------------------------
// Kernel 2: top-k + mean pool. Single block, PDL consumer. (proven)
// Tie-break matches jax.lax.top_k (smaller index wins on equal value).
// ---------------------------------------------------------------------------
__device__ __forceinline__ bool cmp_gt(float av, int ai, float bv, int bi) {
    return (av > bv) || (av == bv && ai < bi);
}

__global__ void __launch_bounds__(256, 1)
topk_mean_kernel(const float* __restrict__ memory_bank,
                 const int* __restrict__ top_k_ptr) {
    __shared__ float s[CAP];                         // 32 KB staged scores
    __shared__ int   chosen[MAXK];
    __shared__ float rv[256];
    __shared__ int   ri[256];

    cudaTriggerProgrammaticLaunchCompletion();
    cudaGridDependencySynchronize();

    int tid = threadIdx.x;

    #pragma unroll
    for (int t = 0; t < CAP / 256; t++) {
        int i = tid + (t << 8);
        s[i] = g_scores[i];
    }
    __syncthreads();

    int k = top_k_ptr[0];
    if (k < 1) k = 1;
    if (k > MAXK) k = MAXK;

    if (k <= 8) {
        float lv[8]; int li[8];
        #pragma unroll
        for (int j = 0; j < 8; j++) { lv[j] = -CUDART_INF_F; li[j] = CAP + j; }

        #pragma unroll 4
        for (int t = 0; t < CAP / 256; t++) {
            int i = tid + (t << 8);
            float v = s[i];
            if (cmp_gt(v, i, lv[7], li[7])) {
                lv[7] = v; li[7] = i;
                #pragma unroll
                for (int j = 7; j > 0; j--) {
                    if (cmp_gt(lv[j], li[j], lv[j-1], li[j-1])) {
                        float tv = lv[j]; lv[j] = lv[j-1]; lv[j-1] = tv;
                        int   ti = li[j]; li[j] = li[j-1]; li[j-1] = ti;
                    }
                }
            }
        }
        __syncthreads();

        float (*sv)[8] = reinterpret_cast<float(*)[8]>(s);
        int   (*si)[8] = reinterpret_cast<int(*)[8]>(s + 2048);
        #pragma unroll
        for (int j = 0; j < 8; j++) { sv[tid][j] = lv[j]; si[tid][j] = li[j]; }
        __syncthreads();

        for (int stride = 128; stride >= 1; stride >>= 1) {
            bool active = (tid < stride);
            float mv[8]; int mi[8];
            if (active) {
                int pa = 0, pb = 0;
                #pragma unroll
                for (int j = 0; j < 8; j++) {
                    float av = sv[tid][pa];          int ai = si[tid][pa];
                    float bv = sv[tid + stride][pb]; int bi = si[tid + stride][pb];
                    if (cmp_gt(av, ai, bv, bi)) { mv[j] = av; mi[j] = ai; pa++; }
                    else                        { mv[j] = bv; mi[j] = bi; pb++; }
                }
            }
            __syncthreads();
            if (active) {
                #pragma unroll
                for (int j = 0; j < 8; j++) { sv[tid][j] = mv[j]; si[tid][j] = mi[j]; }
            }
            __syncthreads();
        }
        if (tid < k) chosen[tid] = si[0][tid];
        __syncthreads();
    } else {
        for (int r = 0; r < k; r++) {
            float best = -CUDART_INF_F; int bi = CAP;
            for (int i = tid; i < CAP; i += 256) {
                float v = s[i];
                if (v > best) { best = v; bi = i; }
            }
            rv[tid] = best; ri[tid] = bi;
            __syncthreads();
            for (int off = 128; off > 0; off >>= 1) {
                if (tid < off) {
                    float ov = rv[tid + off]; int oi = ri[tid + off];
                    if (ov > rv[tid] || (ov == rv[tid] && oi < ri[tid])) {
                        rv[tid] = ov; ri[tid] = oi;
                    }
                }
                __syncthreads();
            }
            if (tid == 0) { chosen[r] = ri[0]; s[ri[0]] = -CUDART_INF_F; }
            __syncthreads();
        }
    }

    float invk = 1.0f / (float)k;
    for (int j = tid; j < VEC; j += 256) {
        float4 acc = make_float4(0.f, 0.f, 0.f, 0.f);
        for (int r = 0; r < k; r++) {
            const float4* row4 =
                reinterpret_cast<const float4*>(memory_bank + (size_t)chosen[r] * DIM);
            float4 v = row4[j];
            acc.x += v.x; acc.y += v.y; acc.z += v.z; acc.w += v.w;
        }
        reinterpret_cast<float4*>(g_retrieved)[j] =
            make_float4(acc.x * invk, acc.y * invk, acc.z * invk, acc.w * invk);
    }
}

// ---------------------------------------------------------------------------
// Kernel 3: out = W_dec @ retrieved + b_dec. FOUR rows per block:
// g_retrieved read ONCE per block (registers) -> retrieved L2 traffic
// 64MB -> 16MB; total decode L2 traffic ~80MB (was 128MB).
// ---------------------------------------------------------------------------
__global__ void __launch_bounds__(256, 4)
decode_kernel(const float* __restrict__ W_dec,
              const float* __restrict__ b_dec,
              float* __restrict__ out) {
    int base = blockIdx.x * 4;
    int tid = threadIdx.x;
    const float4* r4 = reinterpret_cast<const float4*>(g_retrieved);

    // prefetch row0's W while topk runs (PDL overlap)
    const float4* w4_0 = reinterpret_cast<const float4*>(W_dec + (size_t)base * DIM);
    float4 p0 = w4_0[tid];
    float4 p1 = w4_0[tid + 256];
    float4 p2 = w4_0[tid + 512];
    float4 p3 = w4_0[tid + 768];

    cudaGridDependencySynchronize();   // g_retrieved now valid

    // retrieved loaded ONCE per block
    float4 r0 = r4[tid];
    float4 r1 = r4[tid + 256];
    float4 r2 = r4[tid + 512];
    float4 r3 = r4[tid + 768];

    float acc0 = p0.x*r0.x + p0.y*r0.y + p0.z*r0.z + p0.w*r0.w
               + p1.x*r1.x + p1.y*r1.y + p1.z*r1.z + p1.w*r1.w
               + p2.x*r2.x + p2.y*r2.y + p2.z*r2.z + p2.w*r2.w
               + p3.x*r3.x + p3.y*r3.y + p3.z*r3.z + p3.w*r3.w;

    float acc[3];
    #pragma unroll
    for (int j = 0; j < 3; j++) {
        const float4* w4 =
            reinterpret_cast<const float4*>(W_dec + (size_t)(base + 1 + j) * DIM);
        float4 w0 = w4[tid];
        float4 w1 = w4[tid + 256];
        float4 w2 = w4[tid + 512];
        float4 w3 = w4[tid + 768];
        acc[j] = w0.x*r0.x + w0.y*r0.y + w0.z*r0.z + w0.w*r0.w
               + w1.x*r1.x + w1.y*r1.y + w1.z*r1.z + w1.w*r1.w
               + w2.x*r2.x + w2.y*r2.y + w2.z*r2.z + w2.w*r2.w
               + w3.x*r3.x + w3.y*r3.y + w3.z*r3.z + w3.w*r3.w;
    }

    float a0 = acc0, a1 = acc[0], a2 = acc[1], a3 = acc[2];
    block_reduce4(a0, a1, a2, a3);
    if (tid == 0) {
        out[base + 0] = a0 + b_dec[base + 0];
        out[base + 1] = a1 + b_dec[base + 1];
        out[base + 2] = a2 + b_dec[base + 2];
        out[base + 3] = a3 + b_dec[base + 3];
    }
}

// ---------------------------------------------------------------------------
extern "C" void kernel_launch(void* const* d_in, const int* in_sizes, int n_in,
                              void* d_out, int out_size) {
    const float* query       = (const float*)d_in[0];
    const float* memory_bank = (const float*)d_in[1];
    const float* importance  = (const float*)d_in[2];
    const float* age         = (const float*)d_in[3];
    const float* W_dec       = (const float*)d_in[4];
    const float* b_dec       = (const float*)d_in[5];
    const int*   top_k       = (const int*)d_in[6];
    float* out = (float*)d_out;

    scores_kernel<<<CAP / 2, 256>>>(query, memory_bank, importance, age, W_dec);

    cudaLaunchAttribute pdl_attr[1];
    pdl_attr[0].id = cudaLaunchAttributeProgrammaticStreamSerialization;
    pdl_attr[0].val.programmaticStreamSerializationAllowed = 1;

    {
        cudaLaunchConfig_t cfg = {};
        cfg.gridDim  = dim3(1, 1, 1);
        cfg.blockDim = dim3(256, 1, 1);
        cfg.attrs    = pdl_attr;
        cfg.numAttrs = 1;
        cudaLaunchKernelEx(&cfg, topk_mean_kernel, memory_bank, top_k);
    }
    {
        cudaLaunchConfig_t cfg = {};
        cfg.gridDim  = dim3(DIM / 4, 1, 1);
        cfg.blockDim = dim3(256, 1, 1);
        cfg.attrs    = pdl_attr;
        cfg.numAttrs = 1;
        cudaLaunchKernelEx(&cfg, decode_kernel, W_dec, b_dec, out);
    }
}

// round 14
// speedup vs baseline: 1.1468x; 1.0791x over previous
#include <cuda_runtime.h>
#include <cuda_bf16.h>
#include <math_constants.h>

#define DIM 4096
#define CAP 8192
#define VEC (DIM / 4)      // 1024 float4 per row
#define MAXK 64
#define TKT 512            // topk threads

// Scratch (no allocations allowed)
__device__ float g_scores[CAP];
__device__ float g_retrieved[DIM];

// ---------------------------------------------------------------------------
// Reduction helpers
// ---------------------------------------------------------------------------
__device__ __forceinline__ void block_reduce4(float& a, float& b, float& c, float& d) {
    __shared__ float sa[8], sb[8], sc[8], sd[8];
    int lane = threadIdx.x & 31;
    int wid  = threadIdx.x >> 5;
    #pragma unroll
    for (int off = 16; off > 0; off >>= 1) {
        a += __shfl_down_sync(0xffffffffu, a, off);
        b += __shfl_down_sync(0xffffffffu, b, off);
        c += __shfl_down_sync(0xffffffffu, c, off);
        d += __shfl_down_sync(0xffffffffu, d, off);
    }
    if (lane == 0) { sa[wid] = a; sb[wid] = b; sc[wid] = c; sd[wid] = d; }
    __syncthreads();
    if (wid == 0) {
        a = (lane < 8) ? sa[lane] : 0.0f;
        b = (lane < 8) ? sb[lane] : 0.0f;
        c = (lane < 8) ? sc[lane] : 0.0f;
        d = (lane < 8) ? sd[lane] : 0.0f;
        #pragma unroll
        for (int off = 4; off > 0; off >>= 1) {
            a += __shfl_down_sync(0xffffffffu, a, off);
            b += __shfl_down_sync(0xffffffffu, b, off);
            c += __shfl_down_sync(0xffffffffu, c, off);
            d += __shfl_down_sync(0xffffffffu, d, off);
        }
    }
}

__device__ __forceinline__ void block_reduce5(float& a, float& b, float& c,
                                              float& d, float& e) {
    __shared__ float sa[8], sb[8], sc[8], sd[8], se[8];
    int lane = threadIdx.x & 31;
    int wid  = threadIdx.x >> 5;
    #pragma unroll
    for (int off = 16; off > 0; off >>= 1) {
        a += __shfl_down_sync(0xffffffffu, a, off);
        b += __shfl_down_sync(0xffffffffu, b, off);
        c += __shfl_down_sync(0xffffffffu, c, off);
        d += __shfl_down_sync(0xffffffffu, d, off);
        e += __shfl_down_sync(0xffffffffu, e, off);
    }
    if (lane == 0) { sa[wid] = a; sb[wid] = b; sc[wid] = c; sd[wid] = d; se[wid] = e; }
    __syncthreads();
    if (wid == 0) {
        a = (lane < 8) ? sa[lane] : 0.0f;
        b = (lane < 8) ? sb[lane] : 0.0f;
        c = (lane < 8) ? sc[lane] : 0.0f;
        d = (lane < 8) ? sd[lane] : 0.0f;
        e = (lane < 8) ? se[lane] : 0.0f;
        #pragma unroll
        for (int off = 4; off > 0; off >>= 1) {
            a += __shfl_down_sync(0xffffffffu, a, off);
            b += __shfl_down_sync(0xffffffffu, b, off);
            c += __shfl_down_sync(0xffffffffu, c, off);
            d += __shfl_down_sync(0xffffffffu, d, off);
            e += __shfl_down_sync(0xffffffffu, e, off);
        }
    }
}

// ---------------------------------------------------------------------------
// Kernel 1: weighted cosine scores, block per TWO rows, 8 front-batched
// __ldcs loads per thread + W_dec L2 prefetch. (proven: 33.8us, 75% DRAM)
// ---------------------------------------------------------------------------
__global__ void __launch_bounds__(256, 6)
scores_kernel(const float* __restrict__ query,
              const float* __restrict__ memory_bank,
              const float* __restrict__ importance,
              const float* __restrict__ age,
              const float* __restrict__ W_dec) {
    cudaTriggerProgrammaticLaunchCompletion();
    int row0 = blockIdx.x * 2;
    int row1 = row0 + 1;
    int tid = threadIdx.x;

    // prefetch this block's two 8KB W_dec slices into L2 (128 x 128B lines)
    const char* wslice = reinterpret_cast<const char*>(W_dec)
                       + (size_t)blockIdx.x * 16384;
    if (tid < 128) {
        asm volatile("prefetch.global.L2 [%0];"
                     :: "l"(wslice + (size_t)tid * 128));
    }

    const float4* q4 = reinterpret_cast<const float4*>(query);
    const float4* m0 = reinterpret_cast<const float4*>(memory_bank + (size_t)row0 * DIM);
    const float4* m1 = reinterpret_cast<const float4*>(memory_bank + (size_t)row1 * DIM);

    float4 a0 = __ldcs(m0 + tid);
    float4 a1 = __ldcs(m0 + tid + 256);
    float4 a2 = __ldcs(m0 + tid + 512);
    float4 a3 = __ldcs(m0 + tid + 768);
    float4 b0 = __ldcs(m1 + tid);
    float4 b1 = __ldcs(m1 + tid + 256);
    float4 b2 = __ldcs(m1 + tid + 512);
    float4 b3 = __ldcs(m1 + tid + 768);
    float4 q0 = q4[tid];
    float4 q1 = q4[tid + 256];
    float4 q2 = q4[tid + 512];
    float4 q3 = q4[tid + 768];

    float dot0 = q0.x*a0.x + q0.y*a0.y + q0.z*a0.z + q0.w*a0.w
               + q1.x*a1.x + q1.y*a1.y + q1.z*a1.z + q1.w*a1.w
               + q2.x*a2.x + q2.y*a2.y + q2.z*a2.z + q2.w*a2.w
               + q3.x*a3.x + q3.y*a3.y + q3.z*a3.z + q3.w*a3.w;
    float msq0 = a0.x*a0.x + a0.y*a0.y + a0.z*a0.z + a0.w*a0.w
               + a1.x*a1.x + a1.y*a1.y + a1.z*a1.z + a1.w*a1.w
               + a2.x*a2.x + a2.y*a2.y + a2.z*a2.z + a2.w*a2.w
               + a3.x*a3.x + a3.y*a3.y + a3.z*a3.z + a3.w*a3.w;
    float dot1 = q0.x*b0.x + q0.y*b0.y + q0.z*b0.z + q0.w*b0.w
               + q1.x*b1.x + q1.y*b1.y + q1.z*b1.z + q1.w*b1.w
               + q2.x*b2.x + q2.y*b2.y + q2.z*b2.z + q2.w*b2.w
               + q3.x*b3.x + q3.y*b3.y + q3.z*b3.z + q3.w*b3.w;
    float msq1 = b0.x*b0.x + b0.y*b0.y + b0.z*b0.z + b0.w*b0.w
               + b1.x*b1.x + b1.y*b1.y + b1.z*b1.z + b1.w*b1.w
               + b2.x*b2.x + b2.y*b2.y + b2.z*b2.z + b2.w*b2.w
               + b3.x*b3.x + b3.y*b3.y + b3.z*b3.z + b3.w*b3.w;
    float qsq = q0.x*q0.x + q0.y*q0.y + q0.z*q0.z + q0.w*q0.w
              + q1.x*q1.x + q1.y*q1.y + q1.z*q1.z + q1.w*q1.w
              + q2.x*q2.x + q2.y*q2.y + q2.z*q2.z + q2.w*q2.w
              + q3.x*q3.x + q3.y*q3.y + q3.z*q3.z + q3.w*q3.w;

    block_reduce5(dot0, msq0, dot1, msq1, qsq);
    if (tid == 0) {
        float qn = sqrtf(qsq);
        float s0 = dot0 / fmaxf(qn * sqrtf(msq0), 1e-8f);
        float s1 = dot1 / fmaxf(qn * sqrtf(msq1), 1e-8f);
        g_scores[row0] = s0 * importance[row0] * expf(-0.001f * age[row0]);
        g_scores[row1] = s1 * importance[row1] * expf(-0.001f * age[row1]);
    }
}

// ---------------------------------------------------------------------------
// Kernel 2: top-k + mean pool. Single block, 512 threads, PDL consumer.
// float4 staging, 16-element scan/thread, 9-level merge, k==8 unrolled pool.
// Tie-break matches jax.lax.top_k (smaller index wins on equal value).
// ---------------------------------------------------------------------------
__device__ __forceinline__ bool cmp_gt(float av, int ai, float bv, int bi) {
    return (av > bv) || (av == bv && ai < bi);
}

__global__ void __launch_bounds__(TKT, 1)
topk_mean_kernel(const float* __restrict__ memory_bank,
                 const int* __restrict__ top_k_ptr) {
    __shared__ float s[CAP];                 // 32 KB staged scores / list alias
    __shared__ int   chosen[MAXK];
    __shared__ float rv[TKT];
    __shared__ int   ri[TKT];

    cudaTriggerProgrammaticLaunchCompletion();
    cudaGridDependencySynchronize();

    int tid = threadIdx.x;

    // stage scores via float4: 4 LDG.128 per thread
    {
        const float4* g4 = reinterpret_cast<const float4*>(g_scores);
        float4* s4 = reinterpret_cast<float4*>(s);
        #pragma unroll
        for (int t = 0; t < CAP / 4 / TKT; t++) {   // 4 iterations
            int i = tid + t * TKT;
            s4[i] = g4[i];
        }
    }
    __syncthreads();

    int k = top_k_ptr[0];
    if (k < 1) k = 1;
    if (k > MAXK) k = MAXK;

    if (k <= 8) {
        // -------- per-thread sorted top-8 from 16 smem elements --------
        float lv[8]; int li[8];
        #pragma unroll
        for (int j = 0; j < 8; j++) { lv[j] = -CUDART_INF_F; li[j] = CAP + j; }

        #pragma unroll 4
        for (int t = 0; t < CAP / TKT; t++) {       // 16 iterations
            int i = tid + t * TKT;                  // ascending index order
            float v = s[i];
            if (cmp_gt(v, i, lv[7], li[7])) {
                lv[7] = v; li[7] = i;
                #pragma unroll
                for (int j = 7; j > 0; j--) {
                    if (cmp_gt(lv[j], li[j], lv[j-1], li[j-1])) {
                        float tv = lv[j]; lv[j] = lv[j-1]; lv[j-1] = tv;
                        int   ti = li[j]; li[j] = li[j-1]; li[j-1] = ti;
                    }
                }
            }
        }
        __syncthreads();   // all done reading s; safe to alias

        // alias smem: 512 sorted lists of 8 (val 16KB + idx 16KB) = exactly s
        float (*sv)[8] = reinterpret_cast<float(*)[8]>(s);
        int   (*si)[8] = reinterpret_cast<int(*)[8]>(s + TKT * 8);
        #pragma unroll
        for (int j = 0; j < 8; j++) { sv[tid][j] = lv[j]; si[tid][j] = li[j]; }
        __syncthreads();

        // tree merge 512 -> 1; barriers convergent for all threads
        for (int stride = TKT / 2; stride >= 1; stride >>= 1) {
            bool active = (tid < stride);
            float mv[8]; int mi[8];
            if (active) {
                int pa = 0, pb = 0;
                #pragma unroll
                for (int j = 0; j < 8; j++) {
                    float av = sv[tid][pa];          int ai = si[tid][pa];
                    float bv = sv[tid + stride][pb]; int bi = si[tid + stride][pb];
                    if (cmp_gt(av, ai, bv, bi)) { mv[j] = av; mi[j] = ai; pa++; }
                    else                        { mv[j] = bv; mi[j] = bi; pb++; }
                }
            }
            __syncthreads();
            if (active) {
                #pragma unroll
                for (int j = 0; j < 8; j++) { sv[tid][j] = mv[j]; si[tid][j] = mi[j]; }
            }
            __syncthreads();
        }
        if (tid < k) chosen[tid] = si[0][tid];
        __syncthreads();
    } else {
        // -------- fallback: iterative argmax rounds over staged smem --------
        for (int r = 0; r < k; r++) {
            float best = -CUDART_INF_F; int bi = CAP;
            for (int i = tid; i < CAP; i += TKT) {
                float v = s[i];
                if (v > best) { best = v; bi = i; }
            }
            rv[tid] = best; ri[tid] = bi;
            __syncthreads();
            for (int off = TKT / 2; off > 0; off >>= 1) {
                if (tid < off) {
                    float ov = rv[tid + off]; int oi = ri[tid + off];
                    if (ov > rv[tid] || (ov == rv[tid] && oi < ri[tid])) {
                        rv[tid] = ov; ri[tid] = oi;
                    }
                }
                __syncthreads();
            }
            if (tid == 0) { chosen[r] = ri[0]; s[ri[0]] = -CUDART_INF_F; }
            __syncthreads();
        }
    }

    // mean-pool the k selected rows -> g_retrieved
    if (k == 8) {
        // fully unrolled: 16 independent front-batched loads per thread
        const float4* r0 = reinterpret_cast<const float4*>(memory_bank + (size_t)chosen[0] * DIM);
        const float4* r1 = reinterpret_cast<const float4*>(memory_bank + (size_t)chosen[1] * DIM);
        const float4* r2 = reinterpret_cast<const float4*>(memory_bank + (size_t)chosen[2] * DIM);
        const float4* r3 = reinterpret_cast<const float4*>(memory_bank + (size_t)chosen[3] * DIM);
        const float4* r4p = reinterpret_cast<const float4*>(memory_bank + (size_t)chosen[4] * DIM);
        const float4* r5 = reinterpret_cast<const float4*>(memory_bank + (size_t)chosen[5] * DIM);
        const float4* r6 = reinterpret_cast<const float4*>(memory_bank + (size_t)chosen[6] * DIM);
        const float4* r7 = reinterpret_cast<const float4*>(memory_bank + (size_t)chosen[7] * DIM);
        #pragma unroll
        for (int t = 0; t < VEC / TKT; t++) {       // 2 iterations
            int j = tid + t * TKT;
            float4 v0 = r0[j], v1 = r1[j], v2 = r2[j], v3 = r3[j];
            float4 v4 = r4p[j], v5 = r5[j], v6 = r6[j], v7 = r7[j];
            float4 o;
            o.x = (v0.x + v1.x + v2.x + v3.x + v4.x + v5.x + v6.x + v7.x) * 0.125f;
            o.y = (v0.y + v1.y + v2.y + v3.y + v4.y + v5.y + v6.y + v7.y) * 0.125f;
            o.z = (v0.z + v1.z + v2.z + v3.z + v4.z + v5.z + v6.z + v7.z) * 0.125f;
            o.w = (v0.w + v1.w + v2.w + v3.w + v4.w + v5.w + v6.w + v7.w) * 0.125f;
            reinterpret_cast<float4*>(g_retrieved)[j] = o;
        }
    } else {
        float invk = 1.0f / (float)k;
        for (int j = tid; j < VEC; j += TKT) {
            float4 acc = make_float4(0.f, 0.f, 0.f, 0.f);
            for (int r = 0; r < k; r++) {
                const float4* row4 =
                    reinterpret_cast<const float4*>(memory_bank + (size_t)chosen[r] * DIM);
                float4 v = row4[j];
                acc.x += v.x; acc.y += v.y; acc.z += v.z; acc.w += v.w;
            }
            reinterpret_cast<float4*>(g_retrieved)[j] =
                make_float4(acc.x * invk, acc.y * invk, acc.z * invk, acc.w * invk);
        }
    }
}

// ---------------------------------------------------------------------------
// Kernel 3: out = W_dec @ retrieved + b_dec. FOUR rows per block. (proven)
// ---------------------------------------------------------------------------
__global__ void __launch_bounds__(256, 4)
decode_kernel(const float* __restrict__ W_dec,
              const float* __restrict__ b_dec,
              float* __restrict__ out) {
    int base = blockIdx.x * 4;
    int tid = threadIdx.x;
    const float4* r4 = reinterpret_cast<const float4*>(g_retrieved);

    // prefetch row0's W while topk runs (PDL overlap)
    const float4* w4_0 = reinterpret_cast<const float4*>(W_dec + (size_t)base * DIM);
    float4 p0 = w4_0[tid];
    float4 p1 = w4_0[tid + 256];
    float4 p2 = w4_0[tid + 512];
    float4 p3 = w4_0[tid + 768];

    cudaGridDependencySynchronize();   // g_retrieved now valid

    float4 r0 = r4[tid];
    float4 r1 = r4[tid + 256];
    float4 r2 = r4[tid + 512];
    float4 r3 = r4[tid + 768];

    float acc0 = p0.x*r0.x + p0.y*r0.y + p0.z*r0.z + p0.w*r0.w
               + p1.x*r1.x + p1.y*r1.y + p1.z*r1.z + p1.w*r1.w
               + p2.x*r2.x + p2.y*r2.y + p2.z*r2.z + p2.w*r2.w
               + p3.x*r3.x + p3.y*r3.y + p3.z*r3.z + p3.w*r3.w;

    float acc[3];
    #pragma unroll
    for (int j = 0; j < 3; j++) {
        const float4* w4 =
            reinterpret_cast<const float4*>(W_dec + (size_t)(base + 1 + j) * DIM);
        float4 w0 = w4[tid];
        float4 w1 = w4[tid + 256];
        float4 w2 = w4[tid + 512];
        float4 w3 = w4[tid + 768];
        acc[j] = w0.x*r0.x + w0.y*r0.y + w0.z*r0.z + w0.w*r0.w
               + w1.x*r1.x + w1.y*r1.y + w1.z*r1.z + w1.w*r1.w
               + w2.x*r2.x + w2.y*r2.y + w2.z*r2.z + w2.w*r2.w
               + w3.x*r3.x + w3.y*r3.y + w3.z*r3.z + w3.w*r3.w;
    }

    float a0 = acc0, a1 = acc[0], a2 = acc[1], a3 = acc[2];
    block_reduce4(a0, a1, a2, a3);
    if (tid == 0) {
        out[base + 0] = a0 + b_dec[base + 0];
        out[base + 1] = a1 + b_dec[base + 1];
        out[base + 2] = a2 + b_dec[base + 2];
        out[base + 3] = a3 + b_dec[base + 3];
    }
}

// ---------------------------------------------------------------------------
extern "C" void kernel_launch(void* const* d_in, const int* in_sizes, int n_in,
                              void* d_out, int out_size) {
    const float* query       = (const float*)d_in[0];
    const float* memory_bank = (const float*)d_in[1];
    const float* importance  = (const float*)d_in[2];
    const float* age         = (const float*)d_in[3];
    const float* W_dec       = (const float*)d_in[4];
    const float* b_dec       = (const float*)d_in[5];
    const int*   top_k       = (const int*)d_in[6];
    float* out = (float*)d_out;

    scores_kernel<<<CAP / 2, 256>>>(query, memory_bank, importance, age, W_dec);

    cudaLaunchAttribute pdl_attr[1];
    pdl_attr[0].id = cudaLaunchAttributeProgrammaticStreamSerialization;
    pdl_attr[0].val.programmaticStreamSerializationAllowed = 1;

    {
        cudaLaunchConfig_t cfg = {};
        cfg.gridDim  = dim3(1, 1, 1);
        cfg.blockDim = dim3(TKT, 1, 1);
        cfg.attrs    = pdl_attr;
        cfg.numAttrs = 1;
        cudaLaunchKernelEx(&cfg, topk_mean_kernel, memory_bank, top_k);
    }
    {
        cudaLaunchConfig_t cfg = {};
        cfg.gridDim  = dim3(DIM / 4, 1, 1);
        cfg.blockDim = dim3(256, 1, 1);
        cfg.attrs    = pdl_attr;
        cfg.numAttrs = 1;
        cudaLaunchKernelEx(&cfg, decode_kernel, W_dec, b_dec, out);
    }
}